// round 9
// baseline (speedup 1.0000x reference)
#include <cuda_runtime.h>
#include <math.h>

#define DD 256
#define HH 512
#define BB 128
typedef unsigned long long ull;

__device__ __forceinline__ ull packf2(float lo, float hi) {
    return ((ull)__float_as_uint(hi) << 32) | (ull)__float_as_uint(lo);
}
__device__ __forceinline__ float lof(ull v) { return __uint_as_float((unsigned)v); }
__device__ __forceinline__ float hif(ull v) { return __uint_as_float((unsigned)(v >> 32)); }
__device__ __forceinline__ void ffma2(ull& d, ull a, ull b) {
    asm("fma.rn.f32x2 %0, %1, %2, %0;" : "+l"(d) : "l"(a), "l"(b));
}
__device__ __forceinline__ unsigned ld_acq(const unsigned* p) {
    unsigned v, a = (unsigned)__cvta_generic_to_shared(p);
    asm volatile("ld.acquire.cta.shared.u32 %0, [%1];" : "=r"(v) : "r"(a));
    return v;
}
__device__ __forceinline__ void st_rel(unsigned* p, unsigned v) {
    unsigned a = (unsigned)__cvta_generic_to_shared(p);
    asm volatile("st.release.cta.shared.u32 [%0], %1;" :: "r"(a), "r"(v) : "memory");
}
__device__ __forceinline__ void red_rel_add(unsigned* p) {
    unsigned a = (unsigned)__cvta_generic_to_shared(p);
    asm volatile("red.release.cta.shared.add.u32 [%0], 1;" :: "r"(a) : "memory");
}

// Wide weights, fp32 pairs.
__device__ ulonglong2 g_wA[260 * 512];  // (w0.mu,w0.lv), (w1s0.mu,w1s0.lv)
__device__ ull g_wA2[260 * 512];        // (w1s1.mu, w1s1.lv)
__device__ ull g_wO[260 * 512];         // (wo0, wo1)
__device__ ull g_w3p[2 * 512];
__device__ float g_w3o[2 * 512];
__device__ float g_recS[256 * 40];
__device__ float g_recW[4 * 68];

__device__ __forceinline__ int permf(int p) {
    if (p < 3) return (p == 0) ? 0 : ((p == 1) ? 255 : 510);
    if (p < 6) { int q = p - 3; return (q == 0) ? 1 : ((q == 1) ? 256 : 511); }
    int d = 3 + ((p - 6) >> 1);
    return (((p - 6) & 1) == 0) ? (d - 1) : (d + 254);
}
__device__ __forceinline__ int degf(int p) {
    if (p < 3) return 1;
    if (p < 6) return 2;
    return 3 + ((p - 6) >> 1);
}
__device__ __forceinline__ int Pof(int k) {
    if (k <= 0) return 0;
    if (k == 1) return 3;
    int v = 2 * k + 2;
    return v > HH ? HH : v;
}
__device__ __forceinline__ float elu1(float a) {
    float e = __expf(a) - 1.f;
    return a > 0.f ? a : e;
}

__global__ void setup_kernel(
    const float* __restrict__ W0m, const float* __restrict__ W1m, const float* __restrict__ Wom,
    const float* __restrict__ b0m, const float* __restrict__ b1m,
    const float* __restrict__ W0l, const float* __restrict__ W1l, const float* __restrict__ Wol,
    const float* __restrict__ b0l, const float* __restrict__ b1l,
    const float* __restrict__ bom, const float* __restrict__ bol)
{
    int tid = blockIdx.x * blockDim.x + threadIdx.x;
    int stride = gridDim.x * blockDim.x;

    for (int idx = tid; idx < 256 * 512; idx += stride) {
        int i = idx >> 9, u = idx & 511;
        int du = degf(u), ou = permf(u);
        int onet = u >> 8, ocol = u & 255;
        const float* Wo = onet ? Wol : Wom;

        int w0row = i - 1 < 0 ? 0 : i - 1;
        float m0 = (du >= w0row + 1) ? 1.f : 0.f;
        float w0mu = m0 * W0m[ou * DD + w0row];
        float w0lv = m0 * W0l[ou * DD + w0row];

        int pB = Pof(i - 2);
        float w1s[2][2], wos[2];
#pragma unroll
        for (int s = 0; s < 2; s++) {
            int p = pB + s; if (p > HH - 1) p = HH - 1;
            int op = permf(p), dp = degf(p);
            float m1 = (du >= dp) ? 1.f : 0.f;
            w1s[s][0] = m1 * W1m[ou * HH + op];
            w1s[s][1] = m1 * W1l[ou * HH + op];
            float mo = (ocol >= dp) ? 1.f : 0.f;
            wos[s] = mo * Wo[ocol * HH + op];
        }
        g_wA[i * 512 + u] = make_ulonglong2(packf2(w0mu, w0lv), packf2(w1s[0][0], w1s[0][1]));
        g_wA2[i * 512 + u] = packf2(w1s[1][0], w1s[1][1]);
        g_wO[i * 512 + u] = packf2(wos[0], wos[1]);
    }
    for (int idx = tid; idx < 1024; idx += stride) {
        int j = idx >> 9, u = idx & 511;
        int du = degf(u), ou = permf(u);
        int onet = u >> 8, ocol = u & 255;
        const float* Wo = onet ? Wol : Wom;
        int p = (j == 0) ? 2 : 5;
        int op = permf(p), dp = degf(p);
        float m1 = (du >= dp) ? 1.f : 0.f;
        float mo = (ocol >= dp) ? 1.f : 0.f;
        g_w3p[idx] = packf2(m1 * W1m[ou * HH + op], m1 * W1l[ou * HH + op]);
        g_w3o[idx] = mo * Wo[ocol * HH + op];
    }
    for (int i = tid; i < 256; i += stride) {
        int cB = Pof(i - 1), cc = Pof(i) - cB;
        int pB = Pof(i - 2), cp = Pof(i - 1) - pB;
        {
            float* r = g_recS + i * 40;
            for (int k = 0; k < 40; k++) r[k] = 0.f;
            int c2 = cc < 2 ? cc : 2, p2 = cp < 2 ? cp : 2;
            for (int s = 0; s < c2; s++) {
                int p = permf(cB + s);
                if (i >= 1) { r[0 + 2 * s] = W0m[p * DD + (i - 1)]; r[1 + 2 * s] = W0l[p * DD + (i - 1)]; }
                r[4 + 2 * s] = b0m[p];  r[5 + 2 * s] = b0l[p];
                r[8 + 2 * s] = b1m[p];  r[9 + 2 * s] = b1l[p];
                r[32 + 2 * s] = Wom[i * HH + p]; r[33 + 2 * s] = Wol[i * HH + p];
            }
            for (int sp = 0; sp < p2; sp++) {
                int pp = permf(pB + sp);
                r[28 + 2 * sp] = Wom[i * HH + pp]; r[29 + 2 * sp] = Wol[i * HH + pp];
                for (int sc = 0; sc < c2; sc++) {
                    int g = permf(cB + sc);
                    r[12 + sp * 4 + 2 * sc] = W1m[g * HH + pp];
                    r[13 + sp * 4 + 2 * sc] = W1l[g * HH + pp];
                }
            }
            for (int sp = 0; sp < c2; sp++)
                for (int sc = 0; sc < c2; sc++) {
                    int pp = permf(cB + sp), g = permf(cB + sc);
                    r[20 + sp * 4 + 2 * sc] = W1m[g * HH + pp];
                    r[21 + sp * 4 + 2 * sc] = W1l[g * HH + pp];
                }
            r[36] = bom[i]; r[37] = bol[i];
        }
        if (i < 4) {
            float* r = g_recW + i * 68;
            for (int k = 0; k < 68; k++) r[k] = 0.f;
            for (int s = 0; s < cc; s++) {
                int p = permf(cB + s);
                if (i >= 1) { r[0 + 2 * s] = W0m[p * DD + (i - 1)]; r[1 + 2 * s] = W0l[p * DD + (i - 1)]; }
                r[6 + 2 * s] = b0m[p];  r[7 + 2 * s] = b0l[p];
                r[12 + 2 * s] = b1m[p]; r[13 + 2 * s] = b1l[p];
                r[60 + 2 * s] = Wom[i * HH + p]; r[61 + 2 * s] = Wol[i * HH + p];
            }
            for (int sp = 0; sp < cp; sp++) {
                int pp = permf(pB + sp);
                r[54 + 2 * sp] = Wom[i * HH + pp]; r[55 + 2 * sp] = Wol[i * HH + pp];
                for (int sc = 0; sc < cc; sc++) {
                    int g = permf(cB + sc);
                    r[18 + sp * 6 + 2 * sc] = W1m[g * HH + pp];
                    r[19 + sp * 6 + 2 * sc] = W1l[g * HH + pp];
                }
            }
            for (int sp = 0; sp < cc; sp++)
                for (int sc = 0; sc < cc; sc++) {
                    int pp = permf(cB + sp), g = permf(cB + sc);
                    r[36 + sp * 6 + 2 * sc] = W1m[g * HH + pp];
                    r[37 + sp * 6 + 2 * sc] = W1l[g * HH + pp];
                }
            r[66] = bom[i]; r[67] = bol[i];
        }
    }
}

// dynamic smem layout (float indices)
#define OFF_RECS 0            // 10240
#define OFF_RECW 10240        // 272
#define OFF_XS   10512        // 256
#define OFF_PUB  10768        // 256*16
#define OFF_PAR  14864        // 256*16
#define OFF_CNT  18960        // 256 u32
#define OFF_STEP 19216        // 1 u32
#define SM_FLOATS 19220
#define SMEM_BYTES (SM_FLOATS * 4)

struct CombState {
    float h0p[3][2], h1p[3][2];
    float ncol, lvsum;
};

__device__ __forceinline__ void comb_steady(const float* __restrict__ pr, const float* __restrict__ r,
                                            float xi, CombState& st, float* __restrict__ pu,
                                            float* __restrict__ outp)
{
    float h0c[2][2], h1c[2][2];
#pragma unroll
    for (int s = 0; s < 2; s++)
#pragma unroll
        for (int n = 0; n < 2; n++)
            h0c[s][n] = elu1(pr[4 * s + n] + st.ncol * r[2 * s + n] + r[4 + 2 * s + n]);
#pragma unroll
    for (int sc = 0; sc < 2; sc++)
#pragma unroll
        for (int n = 0; n < 2; n++) {
            float a = pr[4 * sc + 2 + n] + r[8 + 2 * sc + n];
#pragma unroll
            for (int sp = 0; sp < 2; sp++) a = fmaf(st.h0p[sp][n], r[12 + sp * 4 + 2 * sc + n], a);
#pragma unroll
            for (int sp = 0; sp < 2; sp++) a = fmaf(h0c[sp][n], r[20 + sp * 4 + 2 * sc + n], a);
            h1c[sc][n] = elu1(a);
        }
    float mu = pr[12] + r[36];
    float lv = pr[13] + r[37];
#pragma unroll
    for (int sp = 0; sp < 2; sp++) { mu = fmaf(st.h1p[sp][0], r[28 + 2 * sp], mu); lv = fmaf(st.h1p[sp][1], r[29 + 2 * sp], lv); }
#pragma unroll
    for (int sc = 0; sc < 2; sc++) { mu = fmaf(h1c[sc][0], r[32 + 2 * sc], mu); lv = fmaf(h1c[sc][1], r[33 + 2 * sc], lv); }
    float ls = 0.5f * lv;
    float nc = (xi - mu) * __expf(-ls);
    st.lvsum += ls; st.ncol = nc;
    *outp = nc;
    *(ull*)(pu + 0) = packf2(nc, nc);
    *(ull*)(pu + 2) = packf2(h0c[0][0], h0c[0][1]);
    *(ull*)(pu + 4) = packf2(h0c[1][0], h0c[1][1]);
    *(ull*)(pu + 6) = packf2(h1c[0][0], h1c[1][0]);
    *(ull*)(pu + 8) = packf2(h1c[0][1], h1c[1][1]);
#pragma unroll
    for (int s = 0; s < 2; s++)
#pragma unroll
        for (int n = 0; n < 2; n++) { st.h0p[s][n] = h0c[s][n]; st.h1p[s][n] = h1c[s][n]; }
}

__device__ __forceinline__ void comb_warm(const float* __restrict__ pr, const float* __restrict__ r,
                                          float xi, CombState& st, float* __restrict__ pu,
                                          float* __restrict__ outp)
{
    float h0c[3][2], h1c[3][2];
#pragma unroll
    for (int s = 0; s < 3; s++)
#pragma unroll
        for (int n = 0; n < 2; n++) {
            float pa0 = (s < 2) ? pr[4 * s + n] : pr[8 + n];
            h0c[s][n] = elu1(pa0 + st.ncol * r[2 * s + n] + r[6 + 2 * s + n]);
        }
#pragma unroll
    for (int sc = 0; sc < 3; sc++)
#pragma unroll
        for (int n = 0; n < 2; n++) {
            float a = ((sc < 2) ? pr[4 * sc + 2 + n] : pr[10 + n]) + r[12 + 2 * sc + n];
#pragma unroll
            for (int sp = 0; sp < 3; sp++) a = fmaf(st.h0p[sp][n], r[18 + sp * 6 + 2 * sc + n], a);
#pragma unroll
            for (int sp = 0; sp < 3; sp++) a = fmaf(h0c[sp][n], r[36 + sp * 6 + 2 * sc + n], a);
            h1c[sc][n] = elu1(a);
        }
    float mu = pr[12] + r[66];
    float lv = pr[13] + r[67];
#pragma unroll
    for (int sp = 0; sp < 3; sp++) { mu = fmaf(st.h1p[sp][0], r[54 + 2 * sp], mu); lv = fmaf(st.h1p[sp][1], r[55 + 2 * sp], lv); }
#pragma unroll
    for (int sc = 0; sc < 3; sc++) { mu = fmaf(h1c[sc][0], r[60 + 2 * sc], mu); lv = fmaf(h1c[sc][1], r[61 + 2 * sc], lv); }
    float ls = 0.5f * lv;
    float nc = (xi - mu) * __expf(-ls);
    st.lvsum += ls; st.ncol = nc;
    *outp = nc;
    *(ull*)(pu + 0) = packf2(nc, nc);
    *(ull*)(pu + 2) = packf2(h0c[0][0], h0c[0][1]);
    *(ull*)(pu + 4) = packf2(h0c[1][0], h0c[1][1]);
    *(ull*)(pu + 6) = packf2(h1c[0][0], h1c[1][0]);
    *(ull*)(pu + 8) = packf2(h1c[0][1], h1c[1][1]);
    *(ull*)(pu + 10) = packf2(h0c[2][0], h0c[2][1]);
    *(ull*)(pu + 12) = packf2(h1c[2][0], h1c[2][1]);
#pragma unroll
    for (int s = 0; s < 3; s++)
#pragma unroll
        for (int n = 0; n < 2; n++) { st.h0p[s][n] = h0c[s][n]; st.h1p[s][n] = h1c[s][n]; }
}

// 128 CTAs, 544 threads. tid<512: wide stream thread (exits after final publish);
// tid==512: combiner. No per-step barriers — acquire/release flags.
__global__ __launch_bounds__(544, 1) void made_kernel(
    const float* __restrict__ x, float* __restrict__ out)
{
    extern __shared__ __align__(16) float SM[];

    const int tid = threadIdx.x;
    const int b = blockIdx.x;

    {
        const float4* src = (const float4*)g_recS;
        float4* dst = (float4*)(SM + OFF_RECS);
        for (int k = tid; k < (256 * 40) / 4; k += 544) dst[k] = src[k];
        for (int k = tid; k < 4 * 68; k += 544) SM[OFF_RECW + k] = g_recW[k];
        if (tid < 256) SM[OFF_XS + tid] = x[b * DD + tid];
        for (int k = tid; k < 2 * 256 * 16 + 257; k += 544) SM[OFF_PUB + k] = 0.f;
    }
    __syncthreads();

    unsigned* const cnt = (unsigned*)(SM + OFF_CNT);
    unsigned* const stepc = (unsigned*)(SM + OFF_STEP);

    if (tid == 512) {
        // ---- combiner ----
        CombState st;
#pragma unroll
        for (int s = 0; s < 3; s++)
#pragma unroll
            for (int n = 0; n < 2; n++) { st.h0p[s][n] = 0.f; st.h1p[s][n] = 0.f; }
        st.ncol = 0.f; st.lvsum = 0.f;
        float* const outb = out + b * DD;
#pragma unroll 1
        for (int i = 0; i < DD; i++) {
            if (i > 0) {
                const unsigned need = (i <= 2) ? 5u : 4u;
                while (ld_acq(cnt + i) < need) {}
            }
            const float* pr = SM + OFF_PAR + i * 16;
            float* pu = SM + OFF_PUB + i * 16;
            const float xi = SM[OFF_XS + i];
            if (i >= 4) comb_steady(pr, SM + OFF_RECS + i * 40, xi, st, pu, outb + i);
            else        comb_warm(pr, SM + OFF_RECW + i * 68, xi, st, pu, outb + i);
            st_rel(stepc, (unsigned)(i + 1));
        }
        out[BB * DD + b] = st.lvsum;
        return;
    }
    if (tid > 512) return;

    // ---- wide stream thread ----
    const int u = tid;
    const int du = degf(u);
    const int su = u - Pof(du - 1);
    const int onet = (tid >> 8) & 1;
    const int ocol = tid & 255;
    const int pubA = du - 1;
    const int pubO = ocol - 1;
    const int off = (su < 2) ? (su << 2) : 8;
    const int jmax = pubA > pubO ? pubA : pubO;

    ull A0 = 0, A1 = 0, AO = 0;
    float aoutC = 0.f;

    const ulonglong2* wA = g_wA + u;
    const ull* wA2 = g_wA2 + u;
    const ull* wO = g_wO + u;
    ulonglong2 WaB[2]; ull Wa2B[2], WoB[2];
    WaB[0] = wA[0];   Wa2B[0] = wA2[0];   WoB[0] = wO[0];
    WaB[1] = wA[512]; Wa2B[1] = wA2[512]; WoB[1] = wO[512];
    const ull w3p2 = g_w3p[u], w3p3 = g_w3p[512 + u];
    const float w3o2 = g_w3o[u], w3o3 = g_w3o[512 + u];

#pragma unroll 1
    for (int j = 0; j <= jmax; j++) {
        const int bsel = j & 1;
        if (j > 0) {
            unsigned v = ld_acq(stepc);
            if (v < (unsigned)j) {
                const bool tight = ((unsigned)(pubA - j) <= 3u) || ((unsigned)(pubO - j) <= 3u);
                do {
                    if (!tight) __nanosleep(128);
                    v = ld_acq(stepc);
                } while (v < (unsigned)j);
            }
            const float* pb = SM + OFF_PUB + (j - 1) * 16;
            if (j <= pubA) {
                const ull nc2  = *(const ull*)(pb + 0);
                const ull h0s0 = *(const ull*)(pb + 2);
                const ull h0s1 = *(const ull*)(pb + 4);
                ffma2(A0, nc2, WaB[bsel].x);
                ffma2(A1, h0s0, WaB[bsel].y);
                ffma2(A1, h0s1, Wa2B[bsel]);
                if ((unsigned)(j - 2) < 2u) {
                    const ull h0s2 = *(const ull*)(pb + 10);
                    ffma2(A1, h0s2, (j == 2) ? w3p2 : w3p3);
                }
            }
            if (j <= pubO) {
                const ull h1p = *(const ull*)(pb + 6 + 2 * onet);
                ffma2(AO, h1p, WoB[bsel]);
                if ((unsigned)(j - 2) < 2u)
                    aoutC = fmaf(pb[12 + onet], (j == 2) ? w3o2 : w3o3, aoutC);
            }
        }
        if (j == pubA) {
            float* pw = SM + OFF_PAR + (j + 1) * 16 + off;
            *(ull*)(pw + 0) = A0;
            *(ull*)(pw + 2) = A1;
            red_rel_add(cnt + j + 1);
        }
        if (j == pubO) {
            SM[OFF_PAR + (j + 1) * 16 + 12 + onet] = lof(AO) + hif(AO) + aoutC;
            red_rel_add(cnt + j + 1);
        }
        if (j + 2 <= pubA) { WaB[bsel] = wA[(j + 2) << 9]; Wa2B[bsel] = wA2[(j + 2) << 9]; }
        if (j + 2 <= pubO) { WoB[bsel] = wO[(j + 2) << 9]; }
    }
}

extern "C" void kernel_launch(void* const* d_in, const int* in_sizes, int n_in,
                              void* d_out, int out_size) {
    const float* xx   = (const float*)d_in[0];
    const float* muW0 = (const float*)d_in[1];
    const float* mub0 = (const float*)d_in[2];
    const float* muW1 = (const float*)d_in[3];
    const float* mub1 = (const float*)d_in[4];
    const float* muWo = (const float*)d_in[5];
    const float* mubo = (const float*)d_in[6];
    const float* lvW0 = (const float*)d_in[7];
    const float* lvb0 = (const float*)d_in[8];
    const float* lvW1 = (const float*)d_in[9];
    const float* lvb1 = (const float*)d_in[10];
    const float* lvWo = (const float*)d_in[11];
    const float* lvbo = (const float*)d_in[12];
    float* out = (float*)d_out;

    cudaFuncSetAttribute(made_kernel, cudaFuncAttributeMaxDynamicSharedMemorySize, SMEM_BYTES);
    setup_kernel<<<512, 256>>>(muW0, muW1, muWo, mub0, mub1,
                               lvW0, lvW1, lvWo, lvb0, lvb1, mubo, lvbo);
    made_kernel<<<BB, 544, SMEM_BYTES>>>(xx, out);
}

// round 10
// speedup vs baseline: 2.3993x; 2.3993x over previous
#include <cuda_runtime.h>
#include <math.h>

#define DD 256
#define HH 512
#define BB 128
typedef unsigned long long ull;

__device__ __forceinline__ ull packf2(float lo, float hi) {
    return ((ull)__float_as_uint(hi) << 32) | (ull)__float_as_uint(lo);
}
__device__ __forceinline__ float lof(ull v) { return __uint_as_float((unsigned)v); }
__device__ __forceinline__ float hif(ull v) { return __uint_as_float((unsigned)(v >> 32)); }
__device__ __forceinline__ void ffma2(ull& d, ull a, ull b) {
    asm("fma.rn.f32x2 %0, %1, %2, %0;" : "+l"(d) : "l"(a), "l"(b));
}

// Wide weights, fp32 pairs.
__device__ ulonglong2 g_wA[260 * 512];  // (w0.mu,w0.lv), (w1s0.mu,w1s0.lv)
__device__ ull g_wA2[260 * 512];        // (w1s1.mu, w1s1.lv)
__device__ ull g_wO[260 * 512];         // (wo0, wo1)
__device__ ull g_w3p[2 * 512];
__device__ float g_w3o[2 * 512];
__device__ float g_recS[256 * 40];
__device__ float g_recW[4 * 68];

__device__ __forceinline__ int permf(int p) {
    if (p < 3) return (p == 0) ? 0 : ((p == 1) ? 255 : 510);
    if (p < 6) { int q = p - 3; return (q == 0) ? 1 : ((q == 1) ? 256 : 511); }
    int d = 3 + ((p - 6) >> 1);
    return (((p - 6) & 1) == 0) ? (d - 1) : (d + 254);
}
__device__ __forceinline__ int degf(int p) {
    if (p < 3) return 1;
    if (p < 6) return 2;
    return 3 + ((p - 6) >> 1);
}
__device__ __forceinline__ int Pof(int k) {
    if (k <= 0) return 0;
    if (k == 1) return 3;
    int v = 2 * k + 2;
    return v > HH ? HH : v;
}
__device__ __forceinline__ float elu1(float a) {
    float e = __expf(a) - 1.f;
    return a > 0.f ? a : e;
}

__global__ void setup_kernel(
    const float* __restrict__ W0m, const float* __restrict__ W1m, const float* __restrict__ Wom,
    const float* __restrict__ b0m, const float* __restrict__ b1m,
    const float* __restrict__ W0l, const float* __restrict__ W1l, const float* __restrict__ Wol,
    const float* __restrict__ b0l, const float* __restrict__ b1l,
    const float* __restrict__ bom, const float* __restrict__ bol)
{
    int tid = blockIdx.x * blockDim.x + threadIdx.x;
    int stride = gridDim.x * blockDim.x;

    for (int idx = tid; idx < 256 * 512; idx += stride) {
        int i = idx >> 9, u = idx & 511;
        int du = degf(u), ou = permf(u);
        int onet = u >> 8, ocol = u & 255;
        const float* Wo = onet ? Wol : Wom;

        int w0row = i - 1 < 0 ? 0 : i - 1;
        float m0 = (du >= w0row + 1) ? 1.f : 0.f;
        float w0mu = m0 * W0m[ou * DD + w0row];
        float w0lv = m0 * W0l[ou * DD + w0row];

        int pB = Pof(i - 2);
        float w1s[2][2], wos[2];
#pragma unroll
        for (int s = 0; s < 2; s++) {
            int p = pB + s; if (p > HH - 1) p = HH - 1;
            int op = permf(p), dp = degf(p);
            float m1 = (du >= dp) ? 1.f : 0.f;
            w1s[s][0] = m1 * W1m[ou * HH + op];
            w1s[s][1] = m1 * W1l[ou * HH + op];
            float mo = (ocol >= dp) ? 1.f : 0.f;
            wos[s] = mo * Wo[ocol * HH + op];
        }
        g_wA[i * 512 + u] = make_ulonglong2(packf2(w0mu, w0lv), packf2(w1s[0][0], w1s[0][1]));
        g_wA2[i * 512 + u] = packf2(w1s[1][0], w1s[1][1]);
        g_wO[i * 512 + u] = packf2(wos[0], wos[1]);
    }
    for (int idx = tid; idx < 1024; idx += stride) {
        int j = idx >> 9, u = idx & 511;
        int du = degf(u), ou = permf(u);
        int onet = u >> 8, ocol = u & 255;
        const float* Wo = onet ? Wol : Wom;
        int p = (j == 0) ? 2 : 5;
        int op = permf(p), dp = degf(p);
        float m1 = (du >= dp) ? 1.f : 0.f;
        float mo = (ocol >= dp) ? 1.f : 0.f;
        g_w3p[idx] = packf2(m1 * W1m[ou * HH + op], m1 * W1l[ou * HH + op]);
        g_w3o[idx] = mo * Wo[ocol * HH + op];
    }
    for (int i = tid; i < 256; i += stride) {
        int cB = Pof(i - 1), cc = Pof(i) - cB;
        int pB = Pof(i - 2), cp = Pof(i - 1) - pB;
        {
            float* r = g_recS + i * 40;
            for (int k = 0; k < 40; k++) r[k] = 0.f;
            int c2 = cc < 2 ? cc : 2, p2 = cp < 2 ? cp : 2;
            for (int s = 0; s < c2; s++) {
                int p = permf(cB + s);
                if (i >= 1) { r[0 + 2 * s] = W0m[p * DD + (i - 1)]; r[1 + 2 * s] = W0l[p * DD + (i - 1)]; }
                r[4 + 2 * s] = b0m[p];  r[5 + 2 * s] = b0l[p];
                r[8 + 2 * s] = b1m[p];  r[9 + 2 * s] = b1l[p];
                r[32 + 2 * s] = Wom[i * HH + p]; r[33 + 2 * s] = Wol[i * HH + p];
            }
            for (int sp = 0; sp < p2; sp++) {
                int pp = permf(pB + sp);
                r[28 + 2 * sp] = Wom[i * HH + pp]; r[29 + 2 * sp] = Wol[i * HH + pp];
                for (int sc = 0; sc < c2; sc++) {
                    int g = permf(cB + sc);
                    r[12 + sp * 4 + 2 * sc] = W1m[g * HH + pp];
                    r[13 + sp * 4 + 2 * sc] = W1l[g * HH + pp];
                }
            }
            for (int sp = 0; sp < c2; sp++)
                for (int sc = 0; sc < c2; sc++) {
                    int pp = permf(cB + sp), g = permf(cB + sc);
                    r[20 + sp * 4 + 2 * sc] = W1m[g * HH + pp];
                    r[21 + sp * 4 + 2 * sc] = W1l[g * HH + pp];
                }
            r[36] = bom[i]; r[37] = bol[i];
        }
        if (i < 4) {
            float* r = g_recW + i * 68;
            for (int k = 0; k < 68; k++) r[k] = 0.f;
            for (int s = 0; s < cc; s++) {
                int p = permf(cB + s);
                if (i >= 1) { r[0 + 2 * s] = W0m[p * DD + (i - 1)]; r[1 + 2 * s] = W0l[p * DD + (i - 1)]; }
                r[6 + 2 * s] = b0m[p];  r[7 + 2 * s] = b0l[p];
                r[12 + 2 * s] = b1m[p]; r[13 + 2 * s] = b1l[p];
                r[60 + 2 * s] = Wom[i * HH + p]; r[61 + 2 * s] = Wol[i * HH + p];
            }
            for (int sp = 0; sp < cp; sp++) {
                int pp = permf(pB + sp);
                r[54 + 2 * sp] = Wom[i * HH + pp]; r[55 + 2 * sp] = Wol[i * HH + pp];
                for (int sc = 0; sc < cc; sc++) {
                    int g = permf(cB + sc);
                    r[18 + sp * 6 + 2 * sc] = W1m[g * HH + pp];
                    r[19 + sp * 6 + 2 * sc] = W1l[g * HH + pp];
                }
            }
            for (int sp = 0; sp < cc; sp++)
                for (int sc = 0; sc < cc; sc++) {
                    int pp = permf(cB + sp), g = permf(cB + sc);
                    r[36 + sp * 6 + 2 * sc] = W1m[g * HH + pp];
                    r[37 + sp * 6 + 2 * sc] = W1l[g * HH + pp];
                }
            r[66] = bom[i]; r[67] = bol[i];
        }
    }
}

// smem layout (floats), identical to the 107us R7 kernel
#define OFF_RECS 0
#define OFF_RECW 10240
#define OFF_XS   10512
#define OFF_PUB  10768
#define OFF_PAR  10800
#define SM_FLOATS 10832

struct CombState {
    float h0p[3][2], h1p[3][2];
    float ncol, lvsum;
};

__device__ __forceinline__ void comb_steady(const float* __restrict__ pr, const float* __restrict__ r,
                                            float xi, CombState& st, float* __restrict__ pu,
                                            float* __restrict__ outp)
{
    float rr[40];
#pragma unroll
    for (int k = 0; k < 10; k++) *(float4*)(rr + 4 * k) = *(const float4*)(r + 4 * k);
    float pp[16];
#pragma unroll
    for (int k = 0; k < 4; k++) *(float4*)(pp + 4 * k) = *(const float4*)(pr + 4 * k);

    float h0c[2][2], h1c[2][2];
#pragma unroll
    for (int s = 0; s < 2; s++)
#pragma unroll
        for (int n = 0; n < 2; n++)
            h0c[s][n] = elu1(pp[4 * s + n] + st.ncol * rr[2 * s + n] + rr[4 + 2 * s + n]);
#pragma unroll
    for (int sc = 0; sc < 2; sc++)
#pragma unroll
        for (int n = 0; n < 2; n++) {
            float a = pp[4 * sc + 2 + n] + rr[8 + 2 * sc + n];
#pragma unroll
            for (int sp = 0; sp < 2; sp++) a = fmaf(st.h0p[sp][n], rr[12 + sp * 4 + 2 * sc + n], a);
#pragma unroll
            for (int sp = 0; sp < 2; sp++) a = fmaf(h0c[sp][n], rr[20 + sp * 4 + 2 * sc + n], a);
            h1c[sc][n] = elu1(a);
        }
    float mu = pp[12] + rr[36];
    float lv = pp[13] + rr[37];
#pragma unroll
    for (int sp = 0; sp < 2; sp++) { mu = fmaf(st.h1p[sp][0], rr[28 + 2 * sp], mu); lv = fmaf(st.h1p[sp][1], rr[29 + 2 * sp], lv); }
#pragma unroll
    for (int sc = 0; sc < 2; sc++) { mu = fmaf(h1c[sc][0], rr[32 + 2 * sc], mu); lv = fmaf(h1c[sc][1], rr[33 + 2 * sc], lv); }
    float ls = 0.5f * lv;
    float nc = (xi - mu) * __expf(-ls);
    st.lvsum += ls; st.ncol = nc;
    *outp = nc;
    *(ull*)(pu + 0) = packf2(nc, nc);
    *(ull*)(pu + 2) = packf2(h0c[0][0], h0c[0][1]);
    *(ull*)(pu + 4) = packf2(h0c[1][0], h0c[1][1]);
    *(ull*)(pu + 6) = packf2(h1c[0][0], h1c[1][0]);
    *(ull*)(pu + 8) = packf2(h1c[0][1], h1c[1][1]);
#pragma unroll
    for (int s = 0; s < 2; s++)
#pragma unroll
        for (int n = 0; n < 2; n++) { st.h0p[s][n] = h0c[s][n]; st.h1p[s][n] = h1c[s][n]; }
}

__device__ __forceinline__ void comb_warm(const float* __restrict__ pr, const float* __restrict__ r,
                                          float xi, CombState& st, float* __restrict__ pu,
                                          float* __restrict__ outp)
{
    float rr[68];
#pragma unroll
    for (int k = 0; k < 17; k++) *(float4*)(rr + 4 * k) = *(const float4*)(r + 4 * k);
    float pp[16];
#pragma unroll
    for (int k = 0; k < 4; k++) *(float4*)(pp + 4 * k) = *(const float4*)(pr + 4 * k);

    float h0c[3][2], h1c[3][2];
#pragma unroll
    for (int s = 0; s < 3; s++)
#pragma unroll
        for (int n = 0; n < 2; n++) {
            float pa0 = (s < 2) ? pp[4 * s + n] : pp[8 + n];
            h0c[s][n] = elu1(pa0 + st.ncol * rr[2 * s + n] + rr[6 + 2 * s + n]);
        }
#pragma unroll
    for (int sc = 0; sc < 3; sc++)
#pragma unroll
        for (int n = 0; n < 2; n++) {
            float a = ((sc < 2) ? pp[4 * sc + 2 + n] : pp[10 + n]) + rr[12 + 2 * sc + n];
#pragma unroll
            for (int sp = 0; sp < 3; sp++) a = fmaf(st.h0p[sp][n], rr[18 + sp * 6 + 2 * sc + n], a);
#pragma unroll
            for (int sp = 0; sp < 3; sp++) a = fmaf(h0c[sp][n], rr[36 + sp * 6 + 2 * sc + n], a);
            h1c[sc][n] = elu1(a);
        }
    float mu = pp[12] + rr[66];
    float lv = pp[13] + rr[67];
#pragma unroll
    for (int sp = 0; sp < 3; sp++) { mu = fmaf(st.h1p[sp][0], rr[54 + 2 * sp], mu); lv = fmaf(st.h1p[sp][1], rr[55 + 2 * sp], lv); }
#pragma unroll
    for (int sc = 0; sc < 3; sc++) { mu = fmaf(h1c[sc][0], rr[60 + 2 * sc], mu); lv = fmaf(h1c[sc][1], rr[61 + 2 * sc], lv); }
    float ls = 0.5f * lv;
    float nc = (xi - mu) * __expf(-ls);
    st.lvsum += ls; st.ncol = nc;
    *outp = nc;
    *(ull*)(pu + 0) = packf2(nc, nc);
    *(ull*)(pu + 2) = packf2(h0c[0][0], h0c[0][1]);
    *(ull*)(pu + 4) = packf2(h0c[1][0], h0c[1][1]);
    *(ull*)(pu + 6) = packf2(h1c[0][0], h1c[1][0]);
    *(ull*)(pu + 8) = packf2(h1c[0][1], h1c[1][1]);
    *(ull*)(pu + 10) = packf2(h0c[2][0], h0c[2][1]);
    *(ull*)(pu + 12) = packf2(h1c[2][0], h1c[2][1]);
#pragma unroll
    for (int s = 0; s < 3; s++)
#pragma unroll
        for (int n = 0; n < 2; n++) { st.h0p[s][n] = h0c[s][n]; st.h1p[s][n] = h1c[s][n]; }
}

// Wide paired sub-step: thread owns hidden units uA=tid, uB=tid+256 (both nets each)
// and output columns (net0, tid), (net1, tid).
__device__ __forceinline__ void wide_step(
    int i, const float* __restrict__ pb,
    ulonglong2 WaA, ull Wa2A, ulonglong2 WaB, ull Wa2B, ull Wo0, ull Wo1,
    ull& A0a, ull& A1a, ull& A0b, ull& A1b, ull& AO0, ull& AO1,
    float& aC0, float& aC1,
    int pubAa, int pubAb, int pubO, float* __restrict__ par, int offa, int offb,
    ull w3a2, ull w3a3, ull w3b2, ull w3b3,
    float w3oA2, float w3oA3, float w3oB2, float w3oB3)
{
    const bool warm = ((unsigned)(i - 2) < 2u);
    if (i <= pubAb) {  // pubAb >= pubAa always
        const ull nc2  = *(const ull*)(pb + 0);
        const ull h0s0 = *(const ull*)(pb + 2);
        const ull h0s1 = *(const ull*)(pb + 4);
        ull h0s2 = 0;
        if (warm) h0s2 = *(const ull*)(pb + 10);
        if (i <= pubAa) {
            ffma2(A0a, nc2, WaA.x);
            ffma2(A1a, h0s0, WaA.y);
            ffma2(A1a, h0s1, Wa2A);
            if (warm) ffma2(A1a, h0s2, (i == 2) ? w3a2 : w3a3);
            if (i == pubAa) { *(ull*)(par + offa) = A0a; *(ull*)(par + offa + 2) = A1a; }
        }
        ffma2(A0b, nc2, WaB.x);
        ffma2(A1b, h0s0, WaB.y);
        ffma2(A1b, h0s1, Wa2B);
        if (warm) ffma2(A1b, h0s2, (i == 2) ? w3b2 : w3b3);
        if (i == pubAb) { *(ull*)(par + offb) = A0b; *(ull*)(par + offb + 2) = A1b; }
    }
    if (i <= pubO) {
        const ull h1n0 = *(const ull*)(pb + 6);
        const ull h1n1 = *(const ull*)(pb + 8);
        ffma2(AO0, h1n0, Wo0);
        ffma2(AO1, h1n1, Wo1);
        if (warm) {
            aC0 = fmaf(pb[12], (i == 2) ? w3oA2 : w3oA3, aC0);
            aC1 = fmaf(pb[13], (i == 2) ? w3oB2 : w3oB3, aC1);
        }
        if (i == pubO)
            *(ull*)(par + 12) = packf2(lof(AO0) + hif(AO0) + aC0,
                                       lof(AO1) + hif(AO1) + aC1);
    }
}

// 128 CTAs, 288 threads: tid<256 wide pair threads; tid==256 combiner (warp 8, top priority).
__global__ __launch_bounds__(288, 1) void made_kernel(
    const float* __restrict__ x, float* __restrict__ out)
{
    __shared__ __align__(16) float SM[SM_FLOATS];

    const int tid = threadIdx.x;
    const int b = blockIdx.x;

    {
        const float4* src = (const float4*)g_recS;
        float4* dst = (float4*)(SM + OFF_RECS);
        for (int k = tid; k < (256 * 40) / 4; k += 288) dst[k] = src[k];
        for (int k = tid; k < 4 * 68; k += 288) SM[OFF_RECW + k] = g_recW[k];
        if (tid < 256) SM[OFF_XS + tid] = x[b * DD + tid];
        for (int k = tid; k < 64; k += 288) SM[OFF_PUB + k] = 0.f;
    }

    float* const pub0 = SM + OFF_PUB;
    float* const pub1 = SM + OFF_PUB + 16;
    float* const par0 = SM + OFF_PAR;
    float* const par1 = SM + OFF_PAR + 16;

    // ---- wide per-thread constants ----
    const int uA = tid < 256 ? tid : 0;
    const int uB = uA + 256;
    const int duA = degf(uA), duB = degf(uB);
    const int suA = uA - Pof(duA - 1), suB = uB - Pof(duB - 1);
    const int pubAa = duA - 1, pubAb = duB - 1;
    const int pubO = uA - 1;
    const int offa = (suA < 2) ? (suA << 2) : 8;
    const int offb = (suB < 2) ? (suB << 2) : 8;

    ull A0a = 0, A1a = 0, A0b = 0, A1b = 0, AO0 = 0, AO1 = 0;
    float aC0 = 0.f, aC1 = 0.f;

    const ulonglong2* wAa = g_wA + uA;
    const ull* wA2a = g_wA2 + uA;
    const ulonglong2* wAb = g_wA + uB;
    const ull* wA2b = g_wA2 + uB;
    const ull* wOa = g_wO + uA;
    const ull* wOb = g_wO + uB;
    ulonglong2 WaA[2], WaB[2];
    ull Wa2A[2], Wa2B[2], Wo0[2], Wo1[2];
    WaA[0] = wAa[0];   Wa2A[0] = wA2a[0];
    WaA[1] = wAa[512]; Wa2A[1] = wA2a[512];
    WaB[0] = wAb[0];   Wa2B[0] = wA2b[0];
    WaB[1] = wAb[512]; Wa2B[1] = wA2b[512];
    Wo0[0] = wOa[0];   Wo0[1] = wOa[512];
    Wo1[0] = wOb[0];   Wo1[1] = wOb[512];
    const ull w3a2 = g_w3p[uA], w3a3 = g_w3p[512 + uA];
    const ull w3b2 = g_w3p[uB], w3b3 = g_w3p[512 + uB];
    const float w3oA2 = g_w3o[uA], w3oA3 = g_w3o[512 + uA];
    const float w3oB2 = g_w3o[uB], w3oB3 = g_w3o[512 + uB];

    // ---- combiner state ----
    CombState st;
#pragma unroll
    for (int s = 0; s < 3; s++)
#pragma unroll
        for (int n = 0; n < 2; n++) { st.h0p[s][n] = 0.f; st.h1p[s][n] = 0.f; }
    st.ncol = 0.f; st.lvsum = 0.f;

    float* const outb = out + b * DD;

    __syncthreads();

#pragma unroll 1
    for (int i = 0; i < DD; i += 2) {
        // even sub-step: wide consumes pub1 (step i-1), publishes par1 (step i+1);
        // combiner consumes par0 (step i), publishes pub0 (step i)
        if (tid < 256) {
            wide_step(i, pub1, WaA[0], Wa2A[0], WaB[0], Wa2B[0], Wo0[0], Wo1[0],
                      A0a, A1a, A0b, A1b, AO0, AO1, aC0, aC1,
                      pubAa, pubAb, pubO, par1, offa, offb,
                      w3a2, w3a3, w3b2, w3b3, w3oA2, w3oA3, w3oB2, w3oB3);
            if (i + 2 <= pubAa) { WaA[0] = wAa[(i + 2) << 9]; Wa2A[0] = wA2a[(i + 2) << 9]; }
            if (i + 2 <= pubAb) { WaB[0] = wAb[(i + 2) << 9]; Wa2B[0] = wA2b[(i + 2) << 9]; }
            if (i + 2 <= pubO)  { Wo0[0] = wOa[(i + 2) << 9]; Wo1[0] = wOb[(i + 2) << 9]; }
        } else if (tid == 256) {
            const float xi = SM[OFF_XS + i];
            if (i >= 4) comb_steady(par0, SM + OFF_RECS + i * 40, xi, st, pub0, outb + i);
            else        comb_warm(par0, SM + OFF_RECW + i * 68, xi, st, pub0, outb + i);
        }
        __syncthreads();
        // odd sub-step: wide consumes pub0, publishes par0; combiner uses par1/pub1
        if (tid < 256) {
            wide_step(i + 1, pub0, WaA[1], Wa2A[1], WaB[1], Wa2B[1], Wo0[1], Wo1[1],
                      A0a, A1a, A0b, A1b, AO0, AO1, aC0, aC1,
                      pubAa, pubAb, pubO, par0, offa, offb,
                      w3a2, w3a3, w3b2, w3b3, w3oA2, w3oA3, w3oB2, w3oB3);
            if (i + 3 <= pubAa) { WaA[1] = wAa[(i + 3) << 9]; Wa2A[1] = wA2a[(i + 3) << 9]; }
            if (i + 3 <= pubAb) { WaB[1] = wAb[(i + 3) << 9]; Wa2B[1] = wA2b[(i + 3) << 9]; }
            if (i + 3 <= pubO)  { Wo0[1] = wOa[(i + 3) << 9]; Wo1[1] = wOb[(i + 3) << 9]; }
        } else if (tid == 256) {
            const float xi = SM[OFF_XS + i + 1];
            if (i + 1 >= 4) comb_steady(par1, SM + OFF_RECS + (i + 1) * 40, xi, st, pub1, outb + i + 1);
            else            comb_warm(par1, SM + OFF_RECW + (i + 1) * 68, xi, st, pub1, outb + i + 1);
        }
        __syncthreads();
    }

    if (tid == 256) out[BB * DD + b] = st.lvsum;
}

extern "C" void kernel_launch(void* const* d_in, const int* in_sizes, int n_in,
                              void* d_out, int out_size) {
    const float* xx   = (const float*)d_in[0];
    const float* muW0 = (const float*)d_in[1];
    const float* mub0 = (const float*)d_in[2];
    const float* muW1 = (const float*)d_in[3];
    const float* mub1 = (const float*)d_in[4];
    const float* muWo = (const float*)d_in[5];
    const float* mubo = (const float*)d_in[6];
    const float* lvW0 = (const float*)d_in[7];
    const float* lvb0 = (const float*)d_in[8];
    const float* lvW1 = (const float*)d_in[9];
    const float* lvb1 = (const float*)d_in[10];
    const float* lvWo = (const float*)d_in[11];
    const float* lvbo = (const float*)d_in[12];
    float* out = (float*)d_out;

    setup_kernel<<<512, 256>>>(muW0, muW1, muWo, mub0, mub1,
                               lvW0, lvW1, lvWo, lvb0, lvb1, mubo, lvbo);
    made_kernel<<<BB, 288>>>(xx, out);
}

// round 11
// speedup vs baseline: 2.7661x; 1.1529x over previous
#include <cuda_runtime.h>
#include <math.h>

#define DD 256
#define HH 512
#define BB 128
typedef unsigned long long ull;

__device__ __forceinline__ ull packf2(float lo, float hi) {
    return ((ull)__float_as_uint(hi) << 32) | (ull)__float_as_uint(lo);
}
__device__ __forceinline__ float lof(ull v) { return __uint_as_float((unsigned)v); }
__device__ __forceinline__ float hif(ull v) { return __uint_as_float((unsigned)(v >> 32)); }
__device__ __forceinline__ void ffma2(ull& d, ull a, ull b) {
    asm("fma.rn.f32x2 %0, %1, %2, %0;" : "+l"(d) : "l"(a), "l"(b));
}
// Named producer/consumer barriers (count = 544 = 17 warps)
#define BAR_SYNC(id)   asm volatile("bar.sync %0, 544;"   :: "r"(id) : "memory")
#define BAR_ARRIVE(id) asm volatile("bar.arrive %0, 544;" :: "r"(id) : "memory")
#define B_PAR0 1
#define B_PAR1 2
#define B_PUB0 3
#define B_PUB1 4

// Wide weights, fp32 pairs.
__device__ ulonglong2 g_wA[260 * 512];  // (w0.mu,w0.lv), (w1s0.mu,w1s0.lv)
__device__ ull g_wA2[260 * 512];        // (w1s1.mu, w1s1.lv)
__device__ ull g_wO[260 * 512];         // (wo0, wo1)
__device__ ull g_w3p[2 * 512];
__device__ float g_w3o[2 * 512];
__device__ float g_recS[256 * 40];
__device__ float g_recW[4 * 68];

__device__ __forceinline__ int permf(int p) {
    if (p < 3) return (p == 0) ? 0 : ((p == 1) ? 255 : 510);
    if (p < 6) { int q = p - 3; return (q == 0) ? 1 : ((q == 1) ? 256 : 511); }
    int d = 3 + ((p - 6) >> 1);
    return (((p - 6) & 1) == 0) ? (d - 1) : (d + 254);
}
__device__ __forceinline__ int degf(int p) {
    if (p < 3) return 1;
    if (p < 6) return 2;
    return 3 + ((p - 6) >> 1);
}
__device__ __forceinline__ int Pof(int k) {
    if (k <= 0) return 0;
    if (k == 1) return 3;
    int v = 2 * k + 2;
    return v > HH ? HH : v;
}
__device__ __forceinline__ float elu1(float a) {
    float e = __expf(a) - 1.f;
    return a > 0.f ? a : e;
}

__global__ void setup_kernel(
    const float* __restrict__ W0m, const float* __restrict__ W1m, const float* __restrict__ Wom,
    const float* __restrict__ b0m, const float* __restrict__ b1m,
    const float* __restrict__ W0l, const float* __restrict__ W1l, const float* __restrict__ Wol,
    const float* __restrict__ b0l, const float* __restrict__ b1l,
    const float* __restrict__ bom, const float* __restrict__ bol)
{
    int tid = blockIdx.x * blockDim.x + threadIdx.x;
    int stride = gridDim.x * blockDim.x;

    for (int idx = tid; idx < 256 * 512; idx += stride) {
        int i = idx >> 9, u = idx & 511;
        int du = degf(u), ou = permf(u);
        int onet = u >> 8, ocol = u & 255;
        const float* Wo = onet ? Wol : Wom;

        int w0row = i - 1 < 0 ? 0 : i - 1;
        float m0 = (du >= w0row + 1) ? 1.f : 0.f;
        float w0mu = m0 * W0m[ou * DD + w0row];
        float w0lv = m0 * W0l[ou * DD + w0row];

        int pB = Pof(i - 2);
        float w1s[2][2], wos[2];
#pragma unroll
        for (int s = 0; s < 2; s++) {
            int p = pB + s; if (p > HH - 1) p = HH - 1;
            int op = permf(p), dp = degf(p);
            float m1 = (du >= dp) ? 1.f : 0.f;
            w1s[s][0] = m1 * W1m[ou * HH + op];
            w1s[s][1] = m1 * W1l[ou * HH + op];
            float mo = (ocol >= dp) ? 1.f : 0.f;
            wos[s] = mo * Wo[ocol * HH + op];
        }
        g_wA[i * 512 + u] = make_ulonglong2(packf2(w0mu, w0lv), packf2(w1s[0][0], w1s[0][1]));
        g_wA2[i * 512 + u] = packf2(w1s[1][0], w1s[1][1]);
        g_wO[i * 512 + u] = packf2(wos[0], wos[1]);
    }
    for (int idx = tid; idx < 1024; idx += stride) {
        int j = idx >> 9, u = idx & 511;
        int du = degf(u), ou = permf(u);
        int onet = u >> 8, ocol = u & 255;
        const float* Wo = onet ? Wol : Wom;
        int p = (j == 0) ? 2 : 5;
        int op = permf(p), dp = degf(p);
        float m1 = (du >= dp) ? 1.f : 0.f;
        float mo = (ocol >= dp) ? 1.f : 0.f;
        g_w3p[idx] = packf2(m1 * W1m[ou * HH + op], m1 * W1l[ou * HH + op]);
        g_w3o[idx] = mo * Wo[ocol * HH + op];
    }
    for (int i = tid; i < 256; i += stride) {
        int cB = Pof(i - 1), cc = Pof(i) - cB;
        int pB = Pof(i - 2), cp = Pof(i - 1) - pB;
        {
            float* r = g_recS + i * 40;
            for (int k = 0; k < 40; k++) r[k] = 0.f;
            int c2 = cc < 2 ? cc : 2, p2 = cp < 2 ? cp : 2;
            for (int s = 0; s < c2; s++) {
                int p = permf(cB + s);
                if (i >= 1) { r[0 + 2 * s] = W0m[p * DD + (i - 1)]; r[1 + 2 * s] = W0l[p * DD + (i - 1)]; }
                r[4 + 2 * s] = b0m[p];  r[5 + 2 * s] = b0l[p];
                r[8 + 2 * s] = b1m[p];  r[9 + 2 * s] = b1l[p];
                r[32 + 2 * s] = Wom[i * HH + p]; r[33 + 2 * s] = Wol[i * HH + p];
            }
            for (int sp = 0; sp < p2; sp++) {
                int pp = permf(pB + sp);
                r[28 + 2 * sp] = Wom[i * HH + pp]; r[29 + 2 * sp] = Wol[i * HH + pp];
                for (int sc = 0; sc < c2; sc++) {
                    int g = permf(cB + sc);
                    r[12 + sp * 4 + 2 * sc] = W1m[g * HH + pp];
                    r[13 + sp * 4 + 2 * sc] = W1l[g * HH + pp];
                }
            }
            for (int sp = 0; sp < c2; sp++)
                for (int sc = 0; sc < c2; sc++) {
                    int pp = permf(cB + sp), g = permf(cB + sc);
                    r[20 + sp * 4 + 2 * sc] = W1m[g * HH + pp];
                    r[21 + sp * 4 + 2 * sc] = W1l[g * HH + pp];
                }
            r[36] = bom[i]; r[37] = bol[i];
        }
        if (i < 4) {
            float* r = g_recW + i * 68;
            for (int k = 0; k < 68; k++) r[k] = 0.f;
            for (int s = 0; s < cc; s++) {
                int p = permf(cB + s);
                if (i >= 1) { r[0 + 2 * s] = W0m[p * DD + (i - 1)]; r[1 + 2 * s] = W0l[p * DD + (i - 1)]; }
                r[6 + 2 * s] = b0m[p];  r[7 + 2 * s] = b0l[p];
                r[12 + 2 * s] = b1m[p]; r[13 + 2 * s] = b1l[p];
                r[60 + 2 * s] = Wom[i * HH + p]; r[61 + 2 * s] = Wol[i * HH + p];
            }
            for (int sp = 0; sp < cp; sp++) {
                int pp = permf(pB + sp);
                r[54 + 2 * sp] = Wom[i * HH + pp]; r[55 + 2 * sp] = Wol[i * HH + pp];
                for (int sc = 0; sc < cc; sc++) {
                    int g = permf(cB + sc);
                    r[18 + sp * 6 + 2 * sc] = W1m[g * HH + pp];
                    r[19 + sp * 6 + 2 * sc] = W1l[g * HH + pp];
                }
            }
            for (int sp = 0; sp < cc; sp++)
                for (int sc = 0; sc < cc; sc++) {
                    int pp = permf(cB + sp), g = permf(cB + sc);
                    r[36 + sp * 6 + 2 * sc] = W1m[g * HH + pp];
                    r[37 + sp * 6 + 2 * sc] = W1l[g * HH + pp];
                }
            r[66] = bom[i]; r[67] = bol[i];
        }
    }
}

// smem layout (floats), identical to the 107us R7 kernel
#define OFF_RECS 0
#define OFF_RECW 10240
#define OFF_XS   10512
#define OFF_PUB  10768
#define OFF_PAR  10800
#define SM_FLOATS 10832

struct CombState {
    float h0p[3][2], h1p[3][2];
    float ncol, lvsum;
};

__device__ __forceinline__ void comb_steady(const float* __restrict__ pr, const float* __restrict__ r,
                                            float xi, CombState& st, float* __restrict__ pu,
                                            float* __restrict__ outp)
{
    float h0c[2][2], h1c[2][2];
#pragma unroll
    for (int s = 0; s < 2; s++)
#pragma unroll
        for (int n = 0; n < 2; n++)
            h0c[s][n] = elu1(pr[4 * s + n] + st.ncol * r[2 * s + n] + r[4 + 2 * s + n]);
#pragma unroll
    for (int sc = 0; sc < 2; sc++)
#pragma unroll
        for (int n = 0; n < 2; n++) {
            float a = pr[4 * sc + 2 + n] + r[8 + 2 * sc + n];
#pragma unroll
            for (int sp = 0; sp < 2; sp++) a = fmaf(st.h0p[sp][n], r[12 + sp * 4 + 2 * sc + n], a);
#pragma unroll
            for (int sp = 0; sp < 2; sp++) a = fmaf(h0c[sp][n], r[20 + sp * 4 + 2 * sc + n], a);
            h1c[sc][n] = elu1(a);
        }
    float mu = pr[12] + r[36];
    float lv = pr[13] + r[37];
#pragma unroll
    for (int sp = 0; sp < 2; sp++) { mu = fmaf(st.h1p[sp][0], r[28 + 2 * sp], mu); lv = fmaf(st.h1p[sp][1], r[29 + 2 * sp], lv); }
#pragma unroll
    for (int sc = 0; sc < 2; sc++) { mu = fmaf(h1c[sc][0], r[32 + 2 * sc], mu); lv = fmaf(h1c[sc][1], r[33 + 2 * sc], lv); }
    float ls = 0.5f * lv;
    float nc = (xi - mu) * __expf(-ls);
    st.lvsum += ls; st.ncol = nc;
    *outp = nc;
    *(ull*)(pu + 0) = packf2(nc, nc);
    *(ull*)(pu + 2) = packf2(h0c[0][0], h0c[0][1]);
    *(ull*)(pu + 4) = packf2(h0c[1][0], h0c[1][1]);
    *(ull*)(pu + 6) = packf2(h1c[0][0], h1c[1][0]);
    *(ull*)(pu + 8) = packf2(h1c[0][1], h1c[1][1]);
#pragma unroll
    for (int s = 0; s < 2; s++)
#pragma unroll
        for (int n = 0; n < 2; n++) { st.h0p[s][n] = h0c[s][n]; st.h1p[s][n] = h1c[s][n]; }
}

__device__ __forceinline__ void comb_warm(const float* __restrict__ pr, const float* __restrict__ r,
                                          float xi, CombState& st, float* __restrict__ pu,
                                          float* __restrict__ outp)
{
    float h0c[3][2], h1c[3][2];
#pragma unroll
    for (int s = 0; s < 3; s++)
#pragma unroll
        for (int n = 0; n < 2; n++) {
            float pa0 = (s < 2) ? pr[4 * s + n] : pr[8 + n];
            h0c[s][n] = elu1(pa0 + st.ncol * r[2 * s + n] + r[6 + 2 * s + n]);
        }
#pragma unroll
    for (int sc = 0; sc < 3; sc++)
#pragma unroll
        for (int n = 0; n < 2; n++) {
            float a = ((sc < 2) ? pr[4 * sc + 2 + n] : pr[10 + n]) + r[12 + 2 * sc + n];
#pragma unroll
            for (int sp = 0; sp < 3; sp++) a = fmaf(st.h0p[sp][n], r[18 + sp * 6 + 2 * sc + n], a);
#pragma unroll
            for (int sp = 0; sp < 3; sp++) a = fmaf(h0c[sp][n], r[36 + sp * 6 + 2 * sc + n], a);
            h1c[sc][n] = elu1(a);
        }
    float mu = pr[12] + r[66];
    float lv = pr[13] + r[67];
#pragma unroll
    for (int sp = 0; sp < 3; sp++) { mu = fmaf(st.h1p[sp][0], r[54 + 2 * sp], mu); lv = fmaf(st.h1p[sp][1], r[55 + 2 * sp], lv); }
#pragma unroll
    for (int sc = 0; sc < 3; sc++) { mu = fmaf(h1c[sc][0], r[60 + 2 * sc], mu); lv = fmaf(h1c[sc][1], r[61 + 2 * sc], lv); }
    float ls = 0.5f * lv;
    float nc = (xi - mu) * __expf(-ls);
    st.lvsum += ls; st.ncol = nc;
    *outp = nc;
    *(ull*)(pu + 0) = packf2(nc, nc);
    *(ull*)(pu + 2) = packf2(h0c[0][0], h0c[0][1]);
    *(ull*)(pu + 4) = packf2(h0c[1][0], h0c[1][1]);
    *(ull*)(pu + 6) = packf2(h1c[0][0], h1c[1][0]);
    *(ull*)(pu + 8) = packf2(h1c[0][1], h1c[1][1]);
    *(ull*)(pu + 10) = packf2(h0c[2][0], h0c[2][1]);
    *(ull*)(pu + 12) = packf2(h1c[2][0], h1c[2][1]);
#pragma unroll
    for (int s = 0; s < 3; s++)
#pragma unroll
        for (int n = 0; n < 2; n++) { st.h0p[s][n] = h0c[s][n]; st.h1p[s][n] = h1c[s][n]; }
}

__device__ __forceinline__ void wide_step(
    int i, const float* __restrict__ pb, const float* __restrict__ pbh,
    const float* __restrict__ pb12,
    ulonglong2 Wa, ull Wa2, ull Wo,
    ull& A0, ull& A1, ull& AO, float& aoutC,
    int pubA, int pubO, float* __restrict__ pwA, float* __restrict__ pwO,
    ull w3p2, ull w3p3, float w3o2, float w3o3)
{
    if (i <= pubA) {
        const ull nc2  = *(const ull*)(pb + 0);
        const ull h0s0 = *(const ull*)(pb + 2);
        const ull h0s1 = *(const ull*)(pb + 4);
        ffma2(A0, nc2, Wa.x);
        ffma2(A1, h0s0, Wa.y);
        ffma2(A1, h0s1, Wa2);
        if ((unsigned)(i - 2) < 2u) {
            const ull h0s2 = *(const ull*)(pb + 10);
            ffma2(A1, h0s2, (i == 2) ? w3p2 : w3p3);
        }
        if (i == pubA) { *(ull*)(pwA + 0) = A0; *(ull*)(pwA + 2) = A1; }
    }
    if (i <= pubO) {
        const ull h1p = *(const ull*)pbh;
        ffma2(AO, h1p, Wo);
        if ((unsigned)(i - 2) < 2u)
            aoutC = fmaf(*pb12, (i == 2) ? w3o2 : w3o3, aoutC);
        if (i == pubO) *pwO = lof(AO) + hif(AO) + aoutC;
    }
}

// 128 CTAs, 544 threads. tid<512: wide warps; warp 16 (tid>=512): combiner warp,
// lane 0 computes. Producer/consumer split named barriers instead of __syncthreads.
__global__ __launch_bounds__(544, 1) void made_kernel(
    const float* __restrict__ x, float* __restrict__ out)
{
    __shared__ __align__(16) float SM[SM_FLOATS];

    const int tid = threadIdx.x;
    const int b = blockIdx.x;

    {
        const float4* src = (const float4*)g_recS;
        float4* dst = (float4*)(SM + OFF_RECS);
        for (int k = tid; k < (256 * 40) / 4; k += 544) dst[k] = src[k];
        for (int k = tid; k < 4 * 68; k += 544) SM[OFF_RECW + k] = g_recW[k];
        if (tid < 256) SM[OFF_XS + tid] = x[b * DD + tid];
        for (int k = tid; k < 64; k += 544) SM[OFF_PUB + k] = 0.f;
    }
    __syncthreads();  // init visible everywhere before priming

    float* const pub0 = SM + OFF_PUB;
    float* const pub1 = SM + OFF_PUB + 16;
    float* const par0 = SM + OFF_PAR;
    float* const par1 = SM + OFF_PAR + 16;
    float* const outb = out + b * DD;

    if (tid < 512) {
        // ---- wide warps ----
        const int u = tid;
        const int du = degf(u);
        const int su = u - Pof(du - 1);
        const int onet = (tid >> 8) & 1;
        const int ocol = tid & 255;
        const int pubA = du - 1;
        const int pubO = ocol - 1;
        const int off = (su < 2) ? (su << 2) : 8;

        float* const pwA0 = par0 + off;
        float* const pwA1 = par1 + off;
        float* const pwO0 = par0 + 12 + onet;
        float* const pwO1 = par1 + 12 + onet;
        const float* const pbh0 = pub0 + 6 + 2 * onet;
        const float* const pbh1 = pub1 + 6 + 2 * onet;
        const float* const pb120 = pub0 + 12 + onet;
        const float* const pb121 = pub1 + 12 + onet;

        ull A0 = 0, A1 = 0, AO = 0;
        float aoutC = 0.f;

        const ulonglong2* wA = g_wA + u;
        const ull* wA2 = g_wA2 + u;
        const ull* wO = g_wO + u;
        ulonglong2 Wa0 = wA[0],   Wa1 = wA[512];
        ull Wa20 = wA2[0], Wa21 = wA2[512];
        ull Wo0 = wO[0],   Wo1 = wO[512];
        const ull w3p2 = g_w3p[u], w3p3 = g_w3p[512 + u];
        const float w3o2 = g_w3o[u], w3o3 = g_w3o[512 + u];

        BAR_ARRIVE(B_PAR0);  // prime: par0 initial zeros are valid for step 0

#pragma unroll 1
        for (int i = 0; i < DD; i += 2) {
            // even sub-step: consume pub1 (step i-1), publish par1 (step i+1)
            BAR_SYNC(B_PUB1);
            wide_step(i, pub1, pbh1, pb121, Wa0, Wa20, Wo0, A0, A1, AO, aoutC,
                      pubA, pubO, pwA1, pwO1, w3p2, w3p3, w3o2, w3o3);
            __threadfence_block();
            BAR_ARRIVE(B_PAR1);
            if (i + 2 <= pubA) { Wa0 = wA[(i + 2) << 9]; Wa20 = wA2[(i + 2) << 9]; }
            if (i + 2 <= pubO) { Wo0 = wO[(i + 2) << 9]; }
            // odd sub-step: consume pub0 (step i), publish par0 (step i+2)
            BAR_SYNC(B_PUB0);
            wide_step(i + 1, pub0, pbh0, pb120, Wa1, Wa21, Wo1, A0, A1, AO, aoutC,
                      pubA, pubO, pwA0, pwO0, w3p2, w3p3, w3o2, w3o3);
            __threadfence_block();
            BAR_ARRIVE(B_PAR0);
            if (i + 3 <= pubA) { Wa1 = wA[(i + 3) << 9]; Wa21 = wA2[(i + 3) << 9]; }
            if (i + 3 <= pubO) { Wo1 = wO[(i + 3) << 9]; }
        }
    } else {
        // ---- combiner warp (warp 16); lane 0 computes, whole warp does barriers ----
        const bool lead = (tid == 512);
        CombState st;
#pragma unroll
        for (int s = 0; s < 3; s++)
#pragma unroll
            for (int n = 0; n < 2; n++) { st.h0p[s][n] = 0.f; st.h1p[s][n] = 0.f; }
        st.ncol = 0.f; st.lvsum = 0.f;

        BAR_ARRIVE(B_PUB1);  // prime: pub1 initial zeros are valid for wide step 0

#pragma unroll 1
        for (int i = 0; i < DD; i += 2) {
            BAR_SYNC(B_PAR0);
            if (lead) {
                const float xi = SM[OFF_XS + i];
                if (i >= 4) comb_steady(par0, SM + OFF_RECS + i * 40, xi, st, pub0, outb + i);
                else        comb_warm(par0, SM + OFF_RECW + i * 68, xi, st, pub0, outb + i);
            }
            __threadfence_block();
            BAR_ARRIVE(B_PUB0);
            BAR_SYNC(B_PAR1);
            if (lead) {
                const float xi = SM[OFF_XS + i + 1];
                if (i + 1 >= 4) comb_steady(par1, SM + OFF_RECS + (i + 1) * 40, xi, st, pub1, outb + i + 1);
                else            comb_warm(par1, SM + OFF_RECW + (i + 1) * 68, xi, st, pub1, outb + i + 1);
            }
            __threadfence_block();
            BAR_ARRIVE(B_PUB1);
        }
        if (lead) out[BB * DD + b] = st.lvsum;
    }
}

extern "C" void kernel_launch(void* const* d_in, const int* in_sizes, int n_in,
                              void* d_out, int out_size) {
    const float* xx   = (const float*)d_in[0];
    const float* muW0 = (const float*)d_in[1];
    const float* mub0 = (const float*)d_in[2];
    const float* muW1 = (const float*)d_in[3];
    const float* mub1 = (const float*)d_in[4];
    const float* muWo = (const float*)d_in[5];
    const float* mubo = (const float*)d_in[6];
    const float* lvW0 = (const float*)d_in[7];
    const float* lvb0 = (const float*)d_in[8];
    const float* lvW1 = (const float*)d_in[9];
    const float* lvb1 = (const float*)d_in[10];
    const float* lvWo = (const float*)d_in[11];
    const float* lvbo = (const float*)d_in[12];
    float* out = (float*)d_out;

    setup_kernel<<<512, 256>>>(muW0, muW1, muWo, mub0, mub1,
                               lvW0, lvW1, lvWo, lvb0, lvb1, mubo, lvbo);
    made_kernel<<<BB, 544>>>(xx, out);
}